// round 12
// baseline (speedup 1.0000x reference)
#include <cuda_runtime.h>
#include <cstdint>

// SKA forward: out[b, g*16+cg, h, w] = sum_k x_pad[b, g*16+cg, h+di, w+dj] * w[b, cg, k, h, w]
// x (16,512,56,56) f32, w (16,16,9,56,56) f32, out (16,512,56,56) f32.
//
// R12: cp.async.bulk (async-proxy, bypasses L1/MSHR) streams x group-tiles
// (10 rows x 224B, contiguous in gmem) through a 6-slot smem ring paced by
// mbarrier expect_tx. One bulk-copy instruction per stage from one thread.
// Block = (b, cg, 8-row tile); w = 9 float4 in regs amortized over ALL 32
// groups. Vertical halo rows pre-zeroed in smem (edge tiles never overwrite
// them); horizontal halo is a predicated LDS.

#define NB   16
#define NC   512
#define NG   32
#define NCG  16
#define NH   56
#define NW   56
#define NW4  14
#define PLANE   (NH * NW)      // 3136
#define CSTRIDE (NCG * PLANE)  // group stride (floats)
#define HT    8
#define NHT   7
#define SLOTS 6
#define SLOTF (10 * NW)        // 560 floats / slot (10 rows x 56)

__device__ __forceinline__ uint32_t smem_u32(const void* p) {
    uint32_t a;
    asm("{ .reg .u64 t; cvta.to.shared.u64 t, %1; cvt.u32.u64 %0, t; }" : "=r"(a) : "l"(p));
    return a;
}

__global__ __launch_bounds__(128, 7) void ska_kernel(
    const float* __restrict__ x,
    const float* __restrict__ wt,
    float* __restrict__ out)
{
    __shared__ __align__(16) float xs[SLOTS * SLOTF];
    __shared__ __align__(8)  unsigned long long mb[SLOTS];

    const int tid = threadIdx.x;
    const int bid = blockIdx.x;            // (b * NCG + cg) * NHT + ht
    const int ht  = bid % NHT;
    const int cg  = (bid / NHT) % NCG;
    const int b   = bid / (NHT * NCG);
    const int h0  = ht * HT;

    const float* xplane0 = x   + (b * NC + cg) * PLANE;   // group 0 plane
    const float* wbase   = wt  + (b * NCG + cg) * 9 * PLANE;
    float*       oplane0 = out + (b * NC + cg) * PLANE;

    // per-block tile geometry (same for every group/slot)
    const int src_row0 = (ht == 0) ? 0 : h0 - 1;
    const int dst_row0 = (ht == 0) ? 1 : 0;
    const int nrows    = 10 - (ht == 0 ? 1 : 0) - (ht == NHT - 1 ? 1 : 0);
    const uint32_t nbytes = (uint32_t)(nrows * NW * 4);   // multiple of 16

    // ---- zero ring once (edge rows stay zero forever) ----
    for (int i = tid; i < SLOTS * SLOTF; i += 128) xs[i] = 0.f;
    asm volatile("fence.proxy.async.shared::cta;" ::: "memory");

    if (tid == 0) {
#pragma unroll
        for (int s = 0; s < SLOTS; ++s)
            asm volatile("mbarrier.init.shared::cta.b64 [%0], %1;"
                         :: "r"(smem_u32(&mb[s])), "r"(1));
    }
    __syncthreads();

    // issue one bulk copy for group g into slot g%SLOTS (single thread)
    auto issue = [&](int g) {
        const int s = g % SLOTS;
        const uint32_t mba = smem_u32(&mb[s]);
        const uint32_t dst = smem_u32(&xs[s * SLOTF + dst_row0 * NW]);
        const float* src   = xplane0 + g * CSTRIDE + src_row0 * NW;
        asm volatile("mbarrier.arrive.expect_tx.shared::cta.b64 _, [%0], %1;"
                     :: "r"(mba), "r"(nbytes) : "memory");
        asm volatile(
            "cp.async.bulk.shared::cluster.global.mbarrier::complete_tx::bytes "
            "[%0], [%1], %2, [%3];"
            :: "r"(dst), "l"(src), "r"(nbytes), "r"(mba) : "memory");
    };

    if (tid == 0) {
#pragma unroll
        for (int s = 0; s < SLOTS; ++s) issue(s);   // prologue: fill ring
    }

    // ---- per-thread weights (9 float4), amortized over all 32 groups ----
    const int  tr  = tid / NW4;          // 0..7 (+ junk for tid>=112)
    const int  w4  = tid % NW4;
    const int  col = w4 * 4;
    const bool act = (tid < 112);

    float4 wk[9];
    if (act) {
#pragma unroll
        for (int k = 0; k < 9; ++k)
            wk[k] = *reinterpret_cast<const float4*>(
                        wbase + (k * NH + h0 + tr) * NW + col);
    }

    const bool wl = (col > 0);
    const bool wr = (col < NW - 4);
    float* obase = oplane0 + (h0 + tr) * NW + col;

    // ---- main loop over 32 groups ----
    for (int g = 0; g < NG; ++g) {
        // wait for slot g%SLOTS, phase (g/SLOTS)&1
        {
            const uint32_t mba = smem_u32(&mb[g % SLOTS]);
            const uint32_t par = (uint32_t)((g / SLOTS) & 1);
            uint32_t done;
            do {
                asm volatile(
                    "{ .reg .pred p; "
                    "mbarrier.try_wait.parity.acquire.cta.shared::cta.b64 p, [%1], %2, 0x989680; "
                    "selp.b32 %0, 1, 0, p; }"
                    : "=r"(done) : "r"(mba), "r"(par) : "memory");
            } while (!done);
        }

        if (act) {
            const float* sp = xs + (g % SLOTS) * SLOTF;
            float4 a = make_float4(0.f, 0.f, 0.f, 0.f);
#pragma unroll
            for (int di = 0; di < 3; ++di) {
                const float* rp = sp + (tr + di) * NW + col; // slot row tr+di
                const float4 xm = *reinterpret_cast<const float4*>(rp);
                const float  xl = wl ? rp[-1] : 0.f;
                const float  xr = wr ? rp[4]  : 0.f;

                const float4 w0 = wk[di * 3 + 0];
                const float4 w1 = wk[di * 3 + 1];
                const float4 w2 = wk[di * 3 + 2];

                a.x = fmaf(xl,   w0.x, a.x);
                a.y = fmaf(xm.x, w0.y, a.y);
                a.z = fmaf(xm.y, w0.z, a.z);
                a.w = fmaf(xm.z, w0.w, a.w);

                a.x = fmaf(xm.x, w1.x, a.x);
                a.y = fmaf(xm.y, w1.y, a.y);
                a.z = fmaf(xm.z, w1.z, a.z);
                a.w = fmaf(xm.w, w1.w, a.w);

                a.x = fmaf(xm.y, w2.x, a.x);
                a.y = fmaf(xm.z, w2.y, a.y);
                a.z = fmaf(xm.w, w2.z, a.z);
                a.w = fmaf(xr,   w2.w, a.w);
            }
            __stcs(reinterpret_cast<float4*>(obase + g * CSTRIDE), a);
        }

        __syncthreads();                 // all threads done reading the slot
        const int gn = g + SLOTS;
        if (tid == 0 && gn < NG) issue(gn);
    }
}

extern "C" void kernel_launch(void* const* d_in, const int* in_sizes, int n_in,
                              void* d_out, int out_size)
{
    const float* x  = (const float*)d_in[0];
    const float* wt = (const float*)d_in[1];
    float* out      = (float*)d_out;

    const int blocks = NB * NCG * NHT;   // 1792
    ska_kernel<<<blocks, 128>>>(x, wt, out);
}